// round 3
// baseline (speedup 1.0000x reference)
#include <cuda_runtime.h>
#include <cuda_bf16.h>

// DET_PROB hierarchical cumprod expansion.
// Hierarchy: B0=8, B1=16, B2=16 -> 2048 leaves per row.
// out[b, a0*256 + a1*16 + a2] =
//   cumprod(dc0[b])[a0] * cumprod16(dc1[b])[a0,a1] * cumprod16(dc2[b])[g,a2]
// where g = a0*16+a1.
//
// One thread owns one leaf group of 16 (g in [0,128) per row).
// Memory-bound: 273 MB read + 256 MB write.

#define B0 8
#define B1 16
#define B2 16
#define GROUPS_PER_ROW (B0 * B1)   // 128

__global__ __launch_bounds__(256) void det_prob_kernel(
    const float* __restrict__ dc0,
    const float* __restrict__ dc1,
    const float* __restrict__ dc2,
    float* __restrict__ out,
    int n_groups)   // BATCH * 128
{
    int t = blockIdx.x * blockDim.x + threadIdx.x;
    if (t >= n_groups) return;

    int row = t >> 7;          // t / 128
    int g   = t & 127;         // group within row
    int a0  = g >> 4;          // which B0 child
    int a1  = g & 15;          // which B1 child

    // ---- c0 = cumprod(dc0[row])[a0] ----
    // dc0 row is 32 B; all 8 loads are warp-broadcast L1 hits.
    const float* r0 = dc0 + (size_t)row * B0;
    float c0 = 1.0f;
#pragma unroll
    for (int k = 0; k < B0; k++) {
        float v = __ldg(&r0[k]);
        c0 *= (k <= a0) ? v : 1.0f;
    }

    // ---- c1 = cumprod-within-group-16 of dc1[row, a0*16 .. +16][a1] ----
    // 4x float4; within a warp only 2 distinct 64B segments -> broadcast.
    const float4* r1 = (const float4*)(dc1 + (size_t)row * (B0 * B1) + a0 * B1);
    float4 q0 = __ldg(&r1[0]);
    float4 q1 = __ldg(&r1[1]);
    float4 q2 = __ldg(&r1[2]);
    float4 q3 = __ldg(&r1[3]);
    float v1[16] = {q0.x, q0.y, q0.z, q0.w, q1.x, q1.y, q1.z, q1.w,
                    q2.x, q2.y, q2.z, q2.w, q3.x, q3.y, q3.z, q3.w};
    float c1 = 1.0f;
#pragma unroll
    for (int k = 0; k < B1; k++) {
        c1 *= (k <= a1) ? v1[k] : 1.0f;
    }

    float p = c0 * c1;   // prefix carried into the leaf group

    // ---- leaf group: running product over 16 contiguous dc2 values ----
    size_t base = (size_t)row * (B0 * B1 * B2) + (size_t)g * B2;
    const float4* r2 = (const float4*)(dc2 + base);
    float4*       w  = (float4*)(out + base);

    // Front-batch all 4 loads (MLP=4), then the dependent multiply chain.
    float4 x0 = __ldg(&r2[0]);
    float4 x1 = __ldg(&r2[1]);
    float4 x2 = __ldg(&r2[2]);
    float4 x3 = __ldg(&r2[3]);

    float4 o;
    p *= x0.x; o.x = p;  p *= x0.y; o.y = p;
    p *= x0.z; o.z = p;  p *= x0.w; o.w = p;
    w[0] = o;
    p *= x1.x; o.x = p;  p *= x1.y; o.y = p;
    p *= x1.z; o.z = p;  p *= x1.w; o.w = p;
    w[1] = o;
    p *= x2.x; o.x = p;  p *= x2.y; o.y = p;
    p *= x2.z; o.z = p;  p *= x2.w; o.w = p;
    w[2] = o;
    p *= x3.x; o.x = p;  p *= x3.y; o.y = p;
    p *= x3.z; o.z = p;  p *= x3.w; o.w = p;
    w[3] = o;
}

extern "C" void kernel_launch(void* const* d_in, const int* in_sizes, int n_in,
                              void* d_out, int out_size) {
    const float* dc0 = (const float*)d_in[0];
    const float* dc1 = (const float*)d_in[1];
    const float* dc2 = (const float*)d_in[2];
    float* out = (float*)d_out;

    int n_groups = out_size / B2;          // BATCH * 128
    int threads = 256;
    int blocks = (n_groups + threads - 1) / threads;
    det_prob_kernel<<<blocks, threads>>>(dc0, dc1, dc2, out, n_groups);
}